// round 1
// baseline (speedup 1.0000x reference)
#include <cuda_runtime.h>
#include <cstddef>

// FlowNet-C correlation on GB300.
// x1,x2: [4,128,96,96] f32.  out: [4, 41*41, 48, 48] f32.
// out[b, i*41+j, oh, ow] = 1/(128*4) * sum_{c, p,q in {0,1}}
//      x1[b,c,2oh+p,2ow+q] * x2pad[b,c,2oh+p+j, 2ow+q+i]   (pad=20 zeros)

#define BATCH 4
#define CHAN  128
#define HH    96
#define WW    96
#define MD    20
#define KD    41
#define OHH   48
#define OWW   48

#define TILE  8      // pooled tile 8x8
#define JG    7      // j values per CTA (6 groups cover 0..41, j=41 discarded)
#define IGL   21     // i values per CTA (2 groups: [0,21), [21,42), i=41 discarded)
#define CC    8      // channels per smem chunk
#define NCHUNK (CHAN / CC)

#define NTHREADS 224 // 32 lanes (4 owsl x 8 ohl) x 7 warps (j)

// x2 smem: per channel, 21 overlapping row-pairs of 57 f32x2 columns.
// Row stride 59 (odd) + per-row (s>>2)&1 element swizzle -> conflict-free LDS.64.
#define X2_SSTRIDE 59
#define X2_PLANE   (21 * X2_SSTRIDE + 2)   // 1241 u64
#define X1_PLANE   (8 * 17)                 // 8 row-pairs x 17 (padded 16) u64

typedef unsigned long long u64;

__device__ __forceinline__ u64 pack2(float a, float b) {
    u64 r; asm("mov.b64 %0, {%1, %2};" : "=l"(r) : "f"(a), "f"(b)); return r;
}
__device__ __forceinline__ void fma2(u64& d, u64 a, u64 b) {
    asm("fma.rn.f32x2 %0, %1, %2, %0;" : "+l"(d) : "l"(a), "l"(b));
}
__device__ __forceinline__ void unpack2(u64 v, float& x, float& y) {
    asm("mov.b64 {%0, %1}, %2;" : "=f"(x), "=f"(y) : "l"(v));
}

__global__ void __launch_bounds__(NTHREADS, 2)
corr_kernel(const float* __restrict__ x1g, const float* __restrict__ x2g,
            float* __restrict__ outg)
{
    extern __shared__ u64 sm[];
    u64* x2s = sm;                        // CC * X2_PLANE
    u64* x1s = sm + CC * X2_PLANE;        // CC * X1_PLANE

    const int tid  = threadIdx.x;
    const int lane = tid & 31;
    const int tj   = tid >> 5;            // 0..6 : j offset within group
    const int owsl = lane & 3;            // 0..3 : pixel-pair slot along ow
    const int ohl  = lane >> 2;           // 0..7 : pooled row within tile

    const int tileid = blockIdx.x;        // 0..35
    const int tx = tileid % (OWW / TILE);
    const int ty = tileid / (OWW / TILE);
    const int jg = blockIdx.y % 6;
    const int ig = blockIdx.y / 6;        // 0..1
    const int b  = blockIdx.z;

    const int oh0 = ty * TILE, ow0 = tx * TILE;
    const int j0 = jg * JG;
    const int iBase = ig * IGL;

    const int base_r = 2 * oh0 + j0;      // x2pad row of pair s=0
    const int col0   = 2 * ow0;           // x2pad col of local col 0

    u64 acc0[IGL], acc1[IGL];
#pragma unroll
    for (int il = 0; il < IGL; ++il) { acc0[il] = 0ull; acc1[il] = 0ull; }

    const int s = 2 * ohl + tj;           // this thread's row-pair index (0..20)
    const int wbase = 4 * owsl + iBase;   // window start column

    for (int ch = 0; ch < NCHUNK; ++ch) {
        const int c0 = ch * CC;

        // ---- fill x2 row-pair tiles (CC x 21 x 57 f32x2 elements) ----
        for (int t = tid; t < CC * 21 * 57; t += NTHREADS) {
            int c    = t / (21 * 57);
            int r    = t - c * (21 * 57);
            int ss   = r / 57;
            int colL = r - ss * 57;
            int gr = base_r + ss - MD;    // x2 row of pair's first element
            int gc = col0 + colL - MD;
            const float* p2 = x2g + ((size_t)(b * CHAN + c0 + c)) * (HH * WW);
            float v0 = 0.f, v1 = 0.f;
            if ((unsigned)gc < WW) {
                if ((unsigned)gr < HH)       v0 = p2[gr * WW + gc];
                if ((unsigned)(gr + 1) < HH) v1 = p2[(gr + 1) * WW + gc];
            }
            x2s[c * X2_PLANE + ss * X2_SSTRIDE + ((ss >> 2) & 1) + colL] = pack2(v0, v1);
        }
        // ---- fill x1 row-pair tiles (CC x 8 x 16) ----
        for (int t = tid; t < CC * 8 * 16; t += NTHREADS) {
            int c    = t >> 7;
            int r    = t & 127;
            int rp   = r >> 4;
            int colL = r & 15;
            const float* p1 = x1g + ((size_t)(b * CHAN + c0 + c)) * (HH * WW);
            int gr = 2 * oh0 + 2 * rp;
            int gc = col0 + colL;
            x1s[c * X1_PLANE + rp * 17 + colL] = pack2(p1[gr * WW + gc], p1[(gr + 1) * WW + gc]);
        }
        __syncthreads();

        // ---- main loop: 2 pixels x 21 i-values, f32x2 over pooled rows ----
#pragma unroll
        for (int c = 0; c < CC; ++c) {
            const u64* row = &x2s[c * X2_PLANE + s * X2_SSTRIDE + ((s >> 2) & 1)];
            const u64* x1r = &x1s[c * X1_PLANE + ohl * 17 + 4 * owsl];
            u64 a0 = x1r[0], a1 = x1r[1], a2 = x1r[2], a3 = x1r[3];
            u64 w0 = row[wbase], w1 = row[wbase + 1], w2 = row[wbase + 2];
#pragma unroll
            for (int il = 0; il < IGL; ++il) {
                u64 w3 = row[wbase + il + 3];
                fma2(acc0[il], a0, w0);   // pixel A, col q=0
                fma2(acc0[il], a1, w1);   // pixel A, col q=1
                fma2(acc1[il], a2, w2);   // pixel B, col q=0
                fma2(acc1[il], a3, w3);   // pixel B, col q=1
                w0 = w1; w1 = w2; w2 = w3;
            }
        }
        __syncthreads();
    }

    // ---- epilogue: pool-row sum + scale + store ----
    const int j = j0 + tj;
    if (j < KD) {
        const int oh = oh0 + ohl;
        const int owA = ow0 + 2 * owsl;
        const float scale = 1.0f / (CHAN * 4);
#pragma unroll
        for (int il = 0; il < IGL; ++il) {
            int i = iBase + il;
            if (i < KD) {
                int chn = i * KD + j;
                float ax, ay, bx, by;
                unpack2(acc0[il], ax, ay);
                unpack2(acc1[il], bx, by);
                size_t base = (((size_t)b * (KD * KD) + chn) * OHH + oh) * OWW + owA;
                outg[base]     = (ax + ay) * scale;
                outg[base + 1] = (bx + by) * scale;
            }
        }
    }
}

extern "C" void kernel_launch(void* const* d_in, const int* in_sizes, int n_in,
                              void* d_out, int out_size)
{
    (void)in_sizes; (void)n_in; (void)out_size;
    const float* x1 = (const float*)d_in[0];
    const float* x2 = (const float*)d_in[1];
    float* out = (float*)d_out;

    const int smem = (CC * X2_PLANE + CC * X1_PLANE) * (int)sizeof(u64); // 88128 B
    static bool attr_set = false;
    if (!attr_set) {
        cudaFuncSetAttribute(corr_kernel, cudaFuncAttributeMaxDynamicSharedMemorySize, smem);
        attr_set = true;
    }

    dim3 grid(36, 12, BATCH);   // 36 tiles x (6 j-groups * 2 i-groups) x batch
    dim3 block(NTHREADS);
    corr_kernel<<<grid, block, smem>>>(x1, x2, out);
}

// round 2
// speedup vs baseline: 2.3214x; 2.3214x over previous
#include <cuda_runtime.h>
#include <cstddef>

// FlowNet-C correlation on GB300.
// x1,x2: [4,128,96,96] f32.  out: [4, 41*41, 48, 48] f32.
// out[b, i*41+j, oh, ow] = 1/(128*4) * sum_{c, p,q in {0,1}}
//      x1[b,c,2oh+p,2ow+q] * x2pad[b,c,2oh+p+j, 2ow+q+i]   (pad=20 zeros)

#define BATCH 4
#define CHAN  128
#define HH    96
#define WW    96
#define MD    20
#define KD    41
#define OHH   48
#define OWW   48

#define TILE  8       // pooled tile 8x8
#define JG    7       // j per CTA (6 groups cover 0..41, j=41 discarded)
#define IGL   21      // i per ig group; warp covers one ig, CTA covers both
#define CC    4       // channels per pipeline chunk
#define NCHUNK (CHAN / CC)   // 32

#define NTHREADS 448  // 14 warps = 7 (j) x 2 (ig); lane = 4 owsl x 8 ohl

// x2 smem: per channel, 21 overlapping row-pairs of 57 f32x2 cols.
// Row stride 59 (odd) + (s>>2)&1 element swizzle -> conflict-free LDS.64.
#define X2_SSTRIDE 59
#define X2_PLANE   (21 * X2_SSTRIDE + 2)   // 1241 u64
#define X1_PLANE   (8 * 17)                // 136 u64
#define BUFSZ      (CC * (X2_PLANE + X1_PLANE))   // 5508 u64 per buffer

typedef unsigned long long u64;

__device__ __forceinline__ u64 pack2(float a, float b) {
    u64 r; asm("mov.b64 %0, {%1, %2};" : "=l"(r) : "f"(a), "f"(b)); return r;
}
__device__ __forceinline__ void fma2(u64& d, u64 a, u64 b) {
    asm("fma.rn.f32x2 %0, %1, %2, %0;" : "+l"(d) : "l"(a), "l"(b));
}
__device__ __forceinline__ void unpack2(u64 v, float& x, float& y) {
    asm("mov.b64 {%0, %1}, %2;" : "=f"(x), "=f"(y) : "l"(v));
}

__global__ void __launch_bounds__(NTHREADS, 1)
corr_kernel(const float* __restrict__ x1g, const float* __restrict__ x2g,
            float* __restrict__ outg)
{
    extern __shared__ u64 sm[];

    const int tid  = threadIdx.x;
    const int lane = tid & 31;
    const int warp = tid >> 5;
    const int tj   = warp % 7;            // j offset within group
    const int ig   = warp / 7;            // 0..1 : i group
    const int owsl = lane & 3;            // pixel-pair slot along ow
    const int ohl  = lane >> 2;           // pooled row within tile

    const int tx = blockIdx.x % (OWW / TILE);
    const int ty = blockIdx.x / (OWW / TILE);
    const int j0 = blockIdx.y * JG;
    const int b  = blockIdx.z;

    const int oh0 = ty * TILE, ow0 = tx * TILE;
    const int base_r = 2 * oh0 + j0;      // x2pad row of pair s=0
    const int col0   = 2 * ow0;           // x2pad col of local col 0

    // ---- divide-free fill precompute: 3 x2 slots / thread / channel ----
    int  off2[3], go2[3];
    bool okA[3], okB[3], okS[3];
#pragma unroll
    for (int k = 0; k < 3; ++k) {
        int t    = tid + k * NTHREADS;    // < 1344 = 21*64
        int ss   = t >> 6;                // row-pair 0..20
        int colL = t & 63;                // padded col; valid < 57
        int gr = base_r + ss - MD;
        int gc = col0 + colL - MD;
        bool okc = (colL < 57) && ((unsigned)gc < WW);
        okA[k] = okc && ((unsigned)gr < HH);
        okB[k] = okc && ((unsigned)(gr + 1) < HH);
        okS[k] = (colL < 57);
        go2[k] = gr * WW + gc;
        off2[k] = ss * X2_SSTRIDE + ((ss >> 2) & 1) + colL;
    }
    // x1 slots: CC*128 = 512 elems; thread handles tid, plus tid+448 if tid<64
    const int n1 = (tid < 64) ? 2 : 1;
    int go1[2], so1[2];
#pragma unroll
    for (int m = 0; m < 2; ++m) {
        int e = tid + m * NTHREADS;       // < 512
        int c = e >> 7, r = e & 127, rp = r >> 4, cl = r & 15;
        go1[m] = c * (HH * WW) + (2 * oh0 + 2 * rp) * WW + col0 + cl;
        so1[m] = c * X1_PLANE + rp * 17 + cl;
    }

    const size_t gbase1 = (size_t)b * CHAN * (HH * WW);

    // fill registers (single staged set: holds chunk ch+1 during COMPUTE(ch))
    float rA[CC][3], rB[CC][3], rU[2], rV[2];

#define LOADCH(CH)                                                           \
    {                                                                        \
        _Pragma("unroll")                                                    \
        for (int c = 0; c < CC; ++c) {                                       \
            const float* p = x2g + gbase1 + ((size_t)((CH) * CC + c)) * (HH * WW); \
            _Pragma("unroll")                                                \
            for (int k = 0; k < 3; ++k) {                                    \
                rA[c][k] = okA[k] ? p[go2[k]] : 0.f;                         \
                rB[c][k] = okB[k] ? p[go2[k] + WW] : 0.f;                    \
            }                                                                \
        }                                                                    \
        const float* q = x1g + gbase1 + (size_t)(CH) * CC * (HH * WW);       \
        _Pragma("unroll")                                                    \
        for (int m = 0; m < 2; ++m)                                          \
            if (m < n1) { rU[m] = q[go1[m]]; rV[m] = q[go1[m] + WW]; }       \
    }

#define STSCH(BUF)                                                           \
    {                                                                        \
        u64* x2s = sm + (BUF) * BUFSZ;                                       \
        u64* x1s = x2s + CC * X2_PLANE;                                      \
        _Pragma("unroll")                                                    \
        for (int c = 0; c < CC; ++c) {                                       \
            _Pragma("unroll")                                                \
            for (int k = 0; k < 3; ++k)                                      \
                if (okS[k]) x2s[c * X2_PLANE + off2[k]] = pack2(rA[c][k], rB[c][k]); \
        }                                                                    \
        _Pragma("unroll")                                                    \
        for (int m = 0; m < 2; ++m)                                          \
            if (m < n1) x1s[so1[m]] = pack2(rU[m], rV[m]);                   \
    }

    // ---- accumulators ----
    u64 acc0[IGL], acc1[IGL];
#pragma unroll
    for (int il = 0; il < IGL; ++il) { acc0[il] = 0ull; acc1[il] = 0ull; }

    const int s = 2 * ohl + tj;                    // this thread's row-pair
    const int rbase = s * X2_SSTRIDE + ((s >> 2) & 1) + 4 * owsl + IGL * ig;
    const int abase = ohl * 17 + 4 * owsl;

    // ---- pipeline prolog ----
    LOADCH(0);
    STSCH(0);
    LOADCH(1);
    __syncthreads();

    for (int ch = 0; ch < NCHUNK; ++ch) {
        if (ch + 1 < NCHUNK) {
            STSCH((ch + 1) & 1);          // store staged chunk ch+1
            if (ch + 2 < NCHUNK) LOADCH(ch + 2);   // refill stage regs
        }
        // ---- compute chunk ch ----
        {
            const u64* x2s = sm + (ch & 1) * BUFSZ;
            const u64* x1s = x2s + CC * X2_PLANE;
#pragma unroll
            for (int c = 0; c < CC; ++c) {
                const u64* row = x2s + c * X2_PLANE + rbase;
                const u64* xr  = x1s + c * X1_PLANE + abase;
                u64 a0 = xr[0], a1 = xr[1], a2 = xr[2], a3 = xr[3];
                u64 w0 = row[0], w1 = row[1], w2 = row[2];
#pragma unroll
                for (int il = 0; il < IGL; ++il) {
                    u64 w3 = row[il + 3];
                    fma2(acc0[il], a0, w0);
                    fma2(acc0[il], a1, w1);
                    fma2(acc1[il], a2, w2);
                    fma2(acc1[il], a3, w3);
                    w0 = w1; w1 = w2; w2 = w3;
                }
            }
        }
        __syncthreads();
    }

    // ---- epilogue ----
    const int j = j0 + tj;
    if (j < KD) {
        const int oh = oh0 + ohl;
        const int owA = ow0 + 2 * owsl;
        const float scale = 1.0f / (CHAN * 4);
#pragma unroll
        for (int il = 0; il < IGL; ++il) {
            int i = IGL * ig + il;
            if (i < KD) {
                int chn = i * KD + j;
                float ax, ay, bx, by;
                unpack2(acc0[il], ax, ay);
                unpack2(acc1[il], bx, by);
                size_t base = (((size_t)b * (KD * KD) + chn) * OHH + oh) * OWW + owA;
                outg[base]     = (ax + ay) * scale;
                outg[base + 1] = (bx + by) * scale;
            }
        }
    }
}

extern "C" void kernel_launch(void* const* d_in, const int* in_sizes, int n_in,
                              void* d_out, int out_size)
{
    (void)in_sizes; (void)n_in; (void)out_size;
    const float* x1 = (const float*)d_in[0];
    const float* x2 = (const float*)d_in[1];
    float* out = (float*)d_out;

    const int smem = 2 * BUFSZ * (int)sizeof(u64);  // 88128 B
    static bool attr_set = false;
    if (!attr_set) {
        cudaFuncSetAttribute(corr_kernel, cudaFuncAttributeMaxDynamicSharedMemorySize, smem);
        attr_set = true;
    }

    dim3 grid(36, 6, BATCH);   // 36 tiles x 6 j-groups x batch
    dim3 block(NTHREADS);
    corr_kernel<<<grid, block, smem>>>(x1, x2, out);
}